// round 13
// baseline (speedup 1.0000x reference)
#include <cuda_runtime.h>

// Problem constants (fixed by reference)
#define BB   4
#define NN   100000
#define KK   16
#define DD   6
#define FF   13
#define LL   3
#define PTS  (BB * NN)          // 400000 points
#define SLOPE 0.2f
#define EPSN  1e-5f

#define CWS  14                 // const row: 13 W1T + 1 pad (16B-aligned pairs)
#define W2S  8                  // smem W2 row: 6 cols + 2 pad
#define TPB  64
#define B1OFF (LL * FF * CWS)   // 546
#define PACKN (B1OFF + LL * FF + 1) // 586 u64

typedef unsigned long long u64;

// W1T + b1 in constant bank (uniform port); W2 goes to SMEM (L1tex port)
__constant__ __align__(16) u64   cwc[PACKN];
__constant__ float csc[3 * LL * DD];   // [0:18) b2, [18:36) gn_w, [36:54) gn_b

// device scratch the prep kernel fills
__device__ u64   g_pack[PACKN];
__device__ u64   g_w2[LL * FF * W2S];
__device__ float g_scal[3 * LL * DD];

// ---- f32x2 packed helpers (sm_103a) ----
__device__ __forceinline__ u64 pk2(float lo, float hi) {
    u64 r;
    asm("mov.b64 %0, {%1, %2};" : "=l"(r) : "f"(lo), "f"(hi));
    return r;
}
__device__ __forceinline__ void up2(u64 v, float& lo, float& hi) {
    asm("mov.b64 {%0, %1}, %2;" : "=f"(lo), "=f"(hi) : "l"(v));
}
__device__ __forceinline__ u64 ffma2(u64 a, u64 b, u64 c) {
    u64 d;
    asm("fma.rn.f32x2 %0, %1, %2, %3;" : "=l"(d) : "l"(a), "l"(b), "l"(c));
    return d;
}
__device__ __forceinline__ u64 fmul2(u64 a, u64 b) {
    u64 d;
    asm("mul.rn.f32x2 %0, %1, %2;" : "=l"(d) : "l"(a), "l"(b));
    return d;
}

__device__ __forceinline__ float leaky(float x) {
    return fmaxf(x, 0.0f) + SLOPE * fminf(x, 0.0f);
}

// packed leaky on both lanes: leaky(x) = 0.6*x + 0.4*|x|
__device__ __forceinline__ u64 leaky2(u64 x, u64 c06, u64 c04) {
    const u64 ax = x & 0x7FFFFFFF7FFFFFFFull;
    return ffma2(ax, c04, fmul2(x, c06));
}

// Pack raw weights into duplicated-(w,w) layouts.
__global__ void prep_kernel(const float* __restrict__ w1g,
                            const float* __restrict__ b1g,
                            const float* __restrict__ w2g,
                            const float* __restrict__ b2g,
                            const float* __restrict__ gnw,
                            const float* __restrict__ gnb)
{
    const int t = threadIdx.x;
    for (int i = t; i < PACKN; i += blockDim.x) g_pack[i] = 0ull;
    for (int i = t; i < LL * FF * W2S; i += blockDim.x) g_w2[i] = 0ull;
    __syncthreads();
    // W1T rows: g_pack[(l*FF+rj)*CWS + ri] = W1[l][ri][rj]
    for (int i = t; i < LL * FF * FF; i += blockDim.x) {
        const int l = i / (FF * FF), r = i % (FF * FF);
        const int ri = r / FF, rj = r % FF;
        const float w = w1g[i];
        g_pack[(l * FF + rj) * CWS + ri] = pk2(w, w);
    }
    // W2 rows: g_w2[(l*FF+ri)*W2S + rj] = W2[l][ri][rj]
    for (int i = t; i < LL * FF * DD; i += blockDim.x) {
        const int l = i / (FF * DD), r = i % (FF * DD);
        const int ri = r / DD, rj = r % DD;
        const float w = w2g[i];
        g_w2[(l * FF + ri) * W2S + rj] = pk2(w, w);
    }
    for (int i = t; i < LL * FF; i += blockDim.x) {
        const float w = b1g[i];
        g_pack[B1OFF + i] = pk2(w, w);
    }
    for (int i = t; i < LL * DD; i += blockDim.x) {
        g_scal[i]                = b2g[i];
        g_scal[LL * DD + i]      = gnw[i];
        g_scal[2 * LL * DD + i]  = gnb[i];
    }
}

__global__ void __launch_bounds__(TPB, 10)
atom_emb_mp_kernel(const float* __restrict__ dist,
                   const float* __restrict__ atomtypes,
                   const u64* __restrict__ w2glob,
                   float* __restrict__ out)
{
    // per-thread h_base scratch, [j][tid] layout: conflict-free 64-bit access
    __shared__ __align__(16) u64 hb[FF * TPB];          // 6656 B
    // W2 packed rows in SMEM (L1tex port, parallel to const port)
    __shared__ __align__(16) u64 sw2[LL * FF * W2S];    // 2496 B

    const int tid = threadIdx.x;
    for (int i = tid; i < LL * FF * W2S; i += TPB) sw2[i] = w2glob[i];
    __syncthreads();

    const int p = blockIdx.x * blockDim.x + tid;
    if (p >= PTS) return;

    const float* atb = atomtypes + (size_t)p * (KK * DD);  // 96 floats, 16B-aligned
    const float* dsb = dist      + (size_t)p * KK;          // 16 floats

    // warm L2 for this point's feature lines while h_base computes
    asm volatile("prefetch.global.L2 [%0];" :: "l"(atb));
    asm volatile("prefetch.global.L2 [%0];" :: "l"(atb + 32));
    asm volatile("prefetch.global.L2 [%0];" :: "l"(atb + 64));
    asm volatile("prefetch.global.L2 [%0];" :: "l"(dsb));

    const u64 C06 = pk2(0.6f, 0.6f);
    const u64 C04 = pk2(0.4f, 0.4f);

    float pe[DD];
    #pragma unroll
    for (int j = 0; j < DD; ++j) pe[j] = 1.0f;

    #pragma unroll 1
    for (int l = 0; l < LL; ++l) {
        const int cb0 = l * FF * CWS;

        u64 pep[DD];
        #pragma unroll
        for (int j = 0; j < DD; ++j) pep[j] = pk2(pe[j], pe[j]);

        // h_base[j] = b1[j] + sum_{i<6} pe[i]*W1[i][j]  -> SMEM scratch hb[j][tid]
        #pragma unroll 1
        for (int j = 0; j < FF; ++j) {
            const ulonglong2* wr = (const ulonglong2*)(cwc + cb0 + j * CWS);
            const ulonglong2 w01 = wr[0];
            const ulonglong2 w23 = wr[1];
            const ulonglong2 w45 = wr[2];
            u64 t = cwc[B1OFF + l * FF + j];
            t = ffma2(pep[0], w01.x, t);
            t = ffma2(pep[1], w01.y, t);
            t = ffma2(pep[2], w23.x, t);
            t = ffma2(pep[3], w23.y, t);
            t = ffma2(pep[4], w45.x, t);
            t = ffma2(pep[5], w45.y, t);
            hb[j * TPB + tid] = t;
        }

        u64 acc[DD];
        #pragma unroll
        for (int j = 0; j < DD; ++j) acc[j] = 0ull;   // (0.0f, 0.0f)

        // 2 iterations; each handles 8 neighbors as FOUR f32x2 streams
        #pragma unroll 1
        for (int kq = 0; kq < KK / 8; ++kq) {
            const float4* ap = (const float4*)(atb + kq * 48);
            const float4 a0  = ap[0];
            const float4 a1  = ap[1];
            const float4 a2  = ap[2];
            const float4 a3  = ap[3];
            const float4 a4  = ap[4];
            const float4 a5  = ap[5];
            const float4 a6  = ap[6];
            const float4 a7  = ap[7];
            const float4 a8  = ap[8];
            const float4 a9  = ap[9];
            const float4 a10 = ap[10];
            const float4 a11 = ap[11];
            const float4 dv0 = *(const float4*)(dsb + kq * 8);
            const float4 dv1 = *(const float4*)(dsb + kq * 8 + 4);

            u64 fA[7], fB[7], fC[7], fD[7];
            fA[0] = pk2(a0.x, a1.z);  fB[0] = pk2(a3.x, a4.z);
            fA[1] = pk2(a0.y, a1.w);  fB[1] = pk2(a3.y, a4.w);
            fA[2] = pk2(a0.z, a2.x);  fB[2] = pk2(a3.z, a5.x);
            fA[3] = pk2(a0.w, a2.y);  fB[3] = pk2(a3.w, a5.y);
            fA[4] = pk2(a1.x, a2.z);  fB[4] = pk2(a4.x, a5.z);
            fA[5] = pk2(a1.y, a2.w);  fB[5] = pk2(a4.y, a5.w);
            fA[6] = pk2(dv0.x, dv0.y); fB[6] = pk2(dv0.z, dv0.w);
            fC[0] = pk2(a6.x, a7.z);  fD[0] = pk2(a9.x, a10.z);
            fC[1] = pk2(a6.y, a7.w);  fD[1] = pk2(a9.y, a10.w);
            fC[2] = pk2(a6.z, a8.x);  fD[2] = pk2(a9.z, a11.x);
            fC[3] = pk2(a6.w, a8.y);  fD[3] = pk2(a9.w, a11.y);
            fC[4] = pk2(a7.x, a8.z);  fD[4] = pk2(a10.x, a11.z);
            fC[5] = pk2(a7.y, a8.w);  fD[5] = pk2(a10.y, a11.w);
            fC[6] = pk2(dv1.x, dv1.y); fD[6] = pk2(dv1.z, dv1.w);

            // rolled j-loop: W1 on the const port, W2 + hb on L1tex —
            // two independent load chains per iteration.
            const u64* hbp  = hb + tid;
            const u64* w2p  = sw2 + l * FF * W2S;
            #pragma unroll 1
            for (int j = 0; j < FF; ++j) {
                const u64* rowp = cwc + cb0 + j * CWS;
                const ulonglong2* wr = (const ulonglong2*)(rowp + 6);
                const ulonglong2 w67 = wr[0];
                const ulonglong2 w89 = wr[1];
                const ulonglong2 wab = wr[2];
                const u64        w12v = rowp[12];

                // W2 row via SMEM (parallel port) — load early
                const ulonglong2* vr = (const ulonglong2*)w2p;
                const ulonglong2 v01 = vr[0];
                const ulonglong2 v23 = vr[1];
                const ulonglong2 v45 = vr[2];

                u64 hA = hbp[0];
                u64 hB = hA, hC = hA, hD = hA;
                hA = ffma2(fA[0], w67.x, hA);  hB = ffma2(fB[0], w67.x, hB);
                hC = ffma2(fC[0], w67.x, hC);  hD = ffma2(fD[0], w67.x, hD);
                hA = ffma2(fA[1], w67.y, hA);  hB = ffma2(fB[1], w67.y, hB);
                hC = ffma2(fC[1], w67.y, hC);  hD = ffma2(fD[1], w67.y, hD);
                hA = ffma2(fA[2], w89.x, hA);  hB = ffma2(fB[2], w89.x, hB);
                hC = ffma2(fC[2], w89.x, hC);  hD = ffma2(fD[2], w89.x, hD);
                hA = ffma2(fA[3], w89.y, hA);  hB = ffma2(fB[3], w89.y, hB);
                hC = ffma2(fC[3], w89.y, hC);  hD = ffma2(fD[3], w89.y, hD);
                hA = ffma2(fA[4], wab.x, hA);  hB = ffma2(fB[4], wab.x, hB);
                hC = ffma2(fC[4], wab.x, hC);  hD = ffma2(fD[4], wab.x, hD);
                hA = ffma2(fA[5], wab.y, hA);  hB = ffma2(fB[5], wab.y, hB);
                hC = ffma2(fC[5], wab.y, hC);  hD = ffma2(fD[5], wab.y, hD);
                hA = ffma2(fA[6], w12v, hA);   hB = ffma2(fB[6], w12v, hB);
                hC = ffma2(fC[6], w12v, hC);   hD = ffma2(fD[6], w12v, hD);

                hA = leaky2(hA, C06, C04);
                hB = leaky2(hB, C06, C04);
                hC = leaky2(hC, C06, C04);
                hD = leaky2(hD, C06, C04);

                acc[0] = ffma2(hA, v01.x, acc[0]);
                acc[1] = ffma2(hA, v01.y, acc[1]);
                acc[2] = ffma2(hA, v23.x, acc[2]);
                acc[3] = ffma2(hA, v23.y, acc[3]);
                acc[4] = ffma2(hA, v45.x, acc[4]);
                acc[5] = ffma2(hA, v45.y, acc[5]);
                acc[0] = ffma2(hB, v01.x, acc[0]);
                acc[1] = ffma2(hB, v01.y, acc[1]);
                acc[2] = ffma2(hB, v23.x, acc[2]);
                acc[3] = ffma2(hB, v23.y, acc[3]);
                acc[4] = ffma2(hB, v45.x, acc[4]);
                acc[5] = ffma2(hB, v45.y, acc[5]);
                acc[0] = ffma2(hC, v01.x, acc[0]);
                acc[1] = ffma2(hC, v01.y, acc[1]);
                acc[2] = ffma2(hC, v23.x, acc[2]);
                acc[3] = ffma2(hC, v23.y, acc[3]);
                acc[4] = ffma2(hC, v45.x, acc[4]);
                acc[5] = ffma2(hC, v45.y, acc[5]);
                acc[0] = ffma2(hD, v01.x, acc[0]);
                acc[1] = ffma2(hD, v01.y, acc[1]);
                acc[2] = ffma2(hD, v23.x, acc[2]);
                acc[3] = ffma2(hD, v23.y, acc[3]);
                acc[4] = ffma2(hD, v45.x, acc[4]);
                acc[5] = ffma2(hD, v45.y, acc[5]);

                hbp += TPB;
                w2p += W2S;
            }
        }

        // reduce the two packed lanes; b2 was added once per k in the ref
        float msg[DD];
        #pragma unroll
        for (int j = 0; j < DD; ++j) {
            float x, y;
            up2(acc[j], x, y);
            msg[j] = x + y + (float)KK * csc[l * DD + j];
        }

        // GroupNorm(2 groups of 3) + leaky + residual
        #pragma unroll
        for (int g = 0; g < 2; ++g) {
            const float m0 = msg[3 * g + 0];
            const float m1 = msg[3 * g + 1];
            const float m2 = msg[3 * g + 2];
            const float mu = (m0 + m1 + m2) * (1.0f / 3.0f);
            const float d0 = m0 - mu, d1 = m1 - mu, d2 = m2 - mu;
            const float var = (d0 * d0 + d1 * d1 + d2 * d2) * (1.0f / 3.0f);
            const float inv = rsqrtf(var + EPSN);
            const float dvv[3] = {d0, d1, d2};
            #pragma unroll
            for (int c = 0; c < 3; ++c) {
                const int ch = 3 * g + c;
                const float v = dvv[c] * inv * csc[LL * DD + l * DD + ch]
                              + csc[2 * LL * DD + l * DD + ch];
                pe[ch] += leaky(v);
            }
        }
    }

    // point_emb out: 6 floats per point, 8B-aligned -> 3x STG.64
    float2* o = (float2*)(out + (size_t)p * DD);
    o[0] = make_float2(pe[0], pe[1]);
    o[1] = make_float2(pe[2], pe[3]);
    o[2] = make_float2(pe[4], pe[5]);
}

extern "C" void kernel_launch(void* const* d_in, const int* in_sizes, int n_in,
                              void* d_out, int out_size)
{
    const float* dist      = (const float*)d_in[0];
    const float* atomtypes = (const float*)d_in[1];
    const float* w1        = (const float*)d_in[2];
    const float* b1        = (const float*)d_in[3];
    const float* w2        = (const float*)d_in[4];
    const float* b2        = (const float*)d_in[5];
    const float* gnw       = (const float*)d_in[6];
    const float* gnb       = (const float*)d_in[7];
    float* out             = (float*)d_out;

    // 1) pack weights into device scratch
    prep_kernel<<<1, 256>>>(w1, b1, w2, b2, gnw, gnb);

    // 2) D2D memcpy into the constant bank (graph-capturable memcpy nodes)
    void* pp = nullptr;
    void* ps = nullptr;
    void* pw2 = nullptr;
    cudaGetSymbolAddress(&pp, g_pack);
    cudaGetSymbolAddress(&ps, g_scal);
    cudaGetSymbolAddress(&pw2, g_w2);
    cudaMemcpyToSymbolAsync(cwc, pp, sizeof(u64) * PACKN, 0,
                            cudaMemcpyDeviceToDevice);
    cudaMemcpyToSymbolAsync(csc, ps, sizeof(float) * 3 * LL * DD, 0,
                            cudaMemcpyDeviceToDevice);

    // 3) main kernel (W2 passed as global pointer; staged to SMEM per CTA)
    const int threads = TPB;
    const int blocks  = (PTS + threads - 1) / threads;
    atom_emb_mp_kernel<<<blocks, threads>>>(dist, atomtypes,
                                            (const u64*)pw2, out);
}

// round 14
// speedup vs baseline: 1.2183x; 1.2183x over previous
#include <cuda_runtime.h>

// Problem constants (fixed by reference)
#define BB   4
#define NN   100000
#define KK   16
#define DD   6
#define FF   13
#define LL   3
#define PTS  (BB * NN)          // 400000 points
#define SLOPE 0.2f
#define EPSN  1e-5f

#define CWS  20                 // combined row: 13 W1T + 1 pad + 6 W2 (16B-aligned pairs)
#define TPB  64
#define B1OFF (LL * FF * CWS)   // 780
#define PACKN (B1OFF + LL * FF + 1) // 820 u64

typedef unsigned long long u64;

// Packed weights: constant bank (uniform-datapath, separate port from L1tex)
__constant__ __align__(16) u64   cwc[PACKN];
__constant__ float csc[3 * LL * DD];   // [0:18) b2, [18:36) gn_w, [36:54) gn_b

// device scratch the prep kernel fills; memcpy'd into the constant bank
__device__ u64   g_pack[PACKN];
__device__ float g_scal[3 * LL * DD];

// ---- f32x2 packed helpers (sm_103a) ----
__device__ __forceinline__ u64 pk2(float lo, float hi) {
    u64 r;
    asm("mov.b64 %0, {%1, %2};" : "=l"(r) : "f"(lo), "f"(hi));
    return r;
}
__device__ __forceinline__ void up2(u64 v, float& lo, float& hi) {
    asm("mov.b64 {%0, %1}, %2;" : "=f"(lo), "=f"(hi) : "l"(v));
}
__device__ __forceinline__ u64 ffma2(u64 a, u64 b, u64 c) {
    u64 d;
    asm("fma.rn.f32x2 %0, %1, %2, %3;" : "=l"(d) : "l"(a), "l"(b), "l"(c));
    return d;
}
__device__ __forceinline__ u64 fmul2(u64 a, u64 b) {
    u64 d;
    asm("mul.rn.f32x2 %0, %1, %2;" : "=l"(d) : "l"(a), "l"(b));
    return d;
}
__device__ __forceinline__ u64 fadd2(u64 a, u64 b) {
    u64 d;
    asm("add.rn.f32x2 %0, %1, %2;" : "=l"(d) : "l"(a), "l"(b));
    return d;
}
__device__ __forceinline__ u64 abs2(u64 x) {
    return x & 0x7FFFFFFF7FFFFFFFull;
}

__device__ __forceinline__ float leaky(float x) {
    return fmaxf(x, 0.0f) + SLOPE * fminf(x, 0.0f);
}

// Pack raw weights into the combined (w,w)-duplicated layout in g_pack.
__global__ void prep_kernel(const float* __restrict__ w1g,
                            const float* __restrict__ b1g,
                            const float* __restrict__ w2g,
                            const float* __restrict__ b2g,
                            const float* __restrict__ gnw,
                            const float* __restrict__ gnb)
{
    const int t = threadIdx.x;
    for (int i = t; i < PACKN; i += blockDim.x) g_pack[i] = 0ull;
    __syncthreads();
    // W1T into combined rows: g_pack[(l*FF+rj)*CWS + ri] = W1[l][ri][rj]
    for (int i = t; i < LL * FF * FF; i += blockDim.x) {
        const int l = i / (FF * FF), r = i % (FF * FF);
        const int ri = r / FF, rj = r % FF;
        const float w = w1g[i];
        g_pack[(l * FF + rj) * CWS + ri] = pk2(w, w);
    }
    // W2 into combined rows: g_pack[(l*FF+ri)*CWS + 14 + rj] = W2[l][ri][rj]
    for (int i = t; i < LL * FF * DD; i += blockDim.x) {
        const int l = i / (FF * DD), r = i % (FF * DD);
        const int ri = r / DD, rj = r % DD;
        const float w = w2g[i];
        g_pack[(l * FF + ri) * CWS + 14 + rj] = pk2(w, w);
    }
    for (int i = t; i < LL * FF; i += blockDim.x) {
        const float w = b1g[i];
        g_pack[B1OFF + i] = pk2(w, w);
    }
    for (int i = t; i < LL * DD; i += blockDim.x) {
        g_scal[i]                = b2g[i];
        g_scal[LL * DD + i]      = gnw[i];
        g_scal[2 * LL * DD + i]  = gnb[i];
    }
}

__global__ void __launch_bounds__(TPB, 10)
atom_emb_mp_kernel(const float* __restrict__ dist,
                   const float* __restrict__ atomtypes,
                   float* __restrict__ out)
{
    // per-thread h_base scratch, [j][tid] layout: conflict-free 64-bit access
    __shared__ __align__(16) u64 hb[FF * TPB];        // 6656 B

    const int tid = threadIdx.x;
    const int p = blockIdx.x * blockDim.x + tid;
    if (p >= PTS) return;

    const float* atb = atomtypes + (size_t)p * (KK * DD);  // 96 floats, 16B-aligned
    const float* dsb = dist      + (size_t)p * KK;          // 16 floats

    const u64 C06 = pk2(0.6f, 0.6f);
    const u64 C04 = pk2(0.4f, 0.4f);

    float pe[DD];
    #pragma unroll
    for (int j = 0; j < DD; ++j) pe[j] = 1.0f;

    #pragma unroll 1
    for (int l = 0; l < LL; ++l) {
        const int cb0 = l * FF * CWS;

        u64 pep[DD];
        #pragma unroll
        for (int j = 0; j < DD; ++j) pep[j] = pk2(pe[j], pe[j]);

        // h_base[j] = b1[j] + sum_{i<6} pe[i]*W1[i][j]  -> SMEM scratch hb[j][tid]
        #pragma unroll 1
        for (int j = 0; j < FF; ++j) {
            const ulonglong2* wr = (const ulonglong2*)(cwc + cb0 + j * CWS);
            const ulonglong2 w01 = wr[0];
            const ulonglong2 w23 = wr[1];
            const ulonglong2 w45 = wr[2];
            u64 t = cwc[B1OFF + l * FF + j];
            t = ffma2(pep[0], w01.x, t);
            t = ffma2(pep[1], w01.y, t);
            t = ffma2(pep[2], w23.x, t);
            t = ffma2(pep[3], w23.y, t);
            t = ffma2(pep[4], w45.x, t);
            t = ffma2(pep[5], w45.y, t);
            hb[j * TPB + tid] = t;
        }

        u64 acc[DD];
        #pragma unroll
        for (int j = 0; j < DD; ++j) acc[j] = 0ull;   // (0.0f, 0.0f)

        // 2 iterations; each handles 8 neighbors as FOUR f32x2 streams
        #pragma unroll 1
        for (int kq = 0; kq < KK / 8; ++kq) {
            const float4* ap = (const float4*)(atb + kq * 48);
            const float4 a0  = ap[0];
            const float4 a1  = ap[1];
            const float4 a2  = ap[2];
            const float4 a3  = ap[3];
            const float4 a4  = ap[4];
            const float4 a5  = ap[5];
            const float4 a6  = ap[6];
            const float4 a7  = ap[7];
            const float4 a8  = ap[8];
            const float4 a9  = ap[9];
            const float4 a10 = ap[10];
            const float4 a11 = ap[11];
            const float4 dv0 = *(const float4*)(dsb + kq * 8);
            const float4 dv1 = *(const float4*)(dsb + kq * 8 + 4);

            u64 fA[7], fB[7], fC[7], fD[7];
            fA[0] = pk2(a0.x, a1.z);  fB[0] = pk2(a3.x, a4.z);
            fA[1] = pk2(a0.y, a1.w);  fB[1] = pk2(a3.y, a4.w);
            fA[2] = pk2(a0.z, a2.x);  fB[2] = pk2(a3.z, a5.x);
            fA[3] = pk2(a0.w, a2.y);  fB[3] = pk2(a3.w, a5.y);
            fA[4] = pk2(a1.x, a2.z);  fB[4] = pk2(a4.x, a5.z);
            fA[5] = pk2(a1.y, a2.w);  fB[5] = pk2(a4.y, a5.w);
            fA[6] = pk2(dv0.x, dv0.y); fB[6] = pk2(dv0.z, dv0.w);
            fC[0] = pk2(a6.x, a7.z);  fD[0] = pk2(a9.x, a10.z);
            fC[1] = pk2(a6.y, a7.w);  fD[1] = pk2(a9.y, a10.w);
            fC[2] = pk2(a6.z, a8.x);  fD[2] = pk2(a9.z, a11.x);
            fC[3] = pk2(a6.w, a8.y);  fD[3] = pk2(a9.w, a11.y);
            fC[4] = pk2(a7.x, a8.z);  fD[4] = pk2(a10.x, a11.z);
            fC[5] = pk2(a7.y, a8.w);  fD[5] = pk2(a10.y, a11.w);
            fC[6] = pk2(dv1.x, dv1.y); fD[6] = pk2(dv1.z, dv1.w);

            // rolled j-loop: weights via const port; sum-before-W2 epilogue.
            const u64* hbp = hb + tid;
            #pragma unroll 1
            for (int j = 0; j < FF; ++j) {
                const u64* rowp = cwc + cb0 + j * CWS;
                const ulonglong2* wr = (const ulonglong2*)(rowp + 6);
                const ulonglong2 w67 = wr[0];
                const ulonglong2 w89 = wr[1];
                const ulonglong2 wab = wr[2];
                const u64        w12v = rowp[12];

                u64 hA = hbp[0];
                u64 hB = hA, hC = hA, hD = hA;
                hA = ffma2(fA[0], w67.x, hA);  hB = ffma2(fB[0], w67.x, hB);
                hC = ffma2(fC[0], w67.x, hC);  hD = ffma2(fD[0], w67.x, hD);
                hA = ffma2(fA[1], w67.y, hA);  hB = ffma2(fB[1], w67.y, hB);
                hC = ffma2(fC[1], w67.y, hC);  hD = ffma2(fD[1], w67.y, hD);
                hA = ffma2(fA[2], w89.x, hA);  hB = ffma2(fB[2], w89.x, hB);
                hC = ffma2(fC[2], w89.x, hC);  hD = ffma2(fD[2], w89.x, hD);
                hA = ffma2(fA[3], w89.y, hA);  hB = ffma2(fB[3], w89.y, hB);
                hC = ffma2(fC[3], w89.y, hC);  hD = ffma2(fD[3], w89.y, hD);
                hA = ffma2(fA[4], wab.x, hA);  hB = ffma2(fB[4], wab.x, hB);
                hC = ffma2(fC[4], wab.x, hC);  hD = ffma2(fD[4], wab.x, hD);
                hA = ffma2(fA[5], wab.y, hA);  hB = ffma2(fB[5], wab.y, hB);
                hC = ffma2(fC[5], wab.y, hC);  hD = ffma2(fD[5], wab.y, hD);
                hA = ffma2(fA[6], w12v, hA);   hB = ffma2(fB[6], w12v, hB);
                hC = ffma2(fC[6], w12v, hC);   hD = ffma2(fD[6], w12v, hD);

                // sum-before-W2:  Σ leaky(h) = 0.6*Σh + 0.4*Σ|h|
                const u64 s  = fadd2(fadd2(hA, hB), fadd2(hC, hD));
                const u64 t2 = fadd2(fadd2(abs2(hA), abs2(hB)),
                                     fadd2(abs2(hC), abs2(hD)));
                const u64 u  = ffma2(t2, C04, fmul2(s, C06));

                const ulonglong2* vr = (const ulonglong2*)(rowp + 14);
                const ulonglong2 v01 = vr[0];
                const ulonglong2 v23 = vr[1];
                const ulonglong2 v45 = vr[2];
                acc[0] = ffma2(u, v01.x, acc[0]);
                acc[1] = ffma2(u, v01.y, acc[1]);
                acc[2] = ffma2(u, v23.x, acc[2]);
                acc[3] = ffma2(u, v23.y, acc[3]);
                acc[4] = ffma2(u, v45.x, acc[4]);
                acc[5] = ffma2(u, v45.y, acc[5]);

                hbp += TPB;
            }
        }

        // reduce the two packed lanes; b2 was added once per k in the ref
        float msg[DD];
        #pragma unroll
        for (int j = 0; j < DD; ++j) {
            float x, y;
            up2(acc[j], x, y);
            msg[j] = x + y + (float)KK * csc[l * DD + j];
        }

        // GroupNorm(2 groups of 3) + leaky + residual
        #pragma unroll
        for (int g = 0; g < 2; ++g) {
            const float m0 = msg[3 * g + 0];
            const float m1 = msg[3 * g + 1];
            const float m2 = msg[3 * g + 2];
            const float mu = (m0 + m1 + m2) * (1.0f / 3.0f);
            const float d0 = m0 - mu, d1 = m1 - mu, d2 = m2 - mu;
            const float var = (d0 * d0 + d1 * d1 + d2 * d2) * (1.0f / 3.0f);
            const float inv = rsqrtf(var + EPSN);
            const float dvv[3] = {d0, d1, d2};
            #pragma unroll
            for (int c = 0; c < 3; ++c) {
                const int ch = 3 * g + c;
                const float v = dvv[c] * inv * csc[LL * DD + l * DD + ch]
                              + csc[2 * LL * DD + l * DD + ch];
                pe[ch] += leaky(v);
            }
        }
    }

    // point_emb out: 6 floats per point, 8B-aligned -> 3x STG.64
    float2* o = (float2*)(out + (size_t)p * DD);
    o[0] = make_float2(pe[0], pe[1]);
    o[1] = make_float2(pe[2], pe[3]);
    o[2] = make_float2(pe[4], pe[5]);
}

extern "C" void kernel_launch(void* const* d_in, const int* in_sizes, int n_in,
                              void* d_out, int out_size)
{
    const float* dist      = (const float*)d_in[0];
    const float* atomtypes = (const float*)d_in[1];
    const float* w1        = (const float*)d_in[2];
    const float* b1        = (const float*)d_in[3];
    const float* w2        = (const float*)d_in[4];
    const float* b2        = (const float*)d_in[5];
    const float* gnw       = (const float*)d_in[6];
    const float* gnb       = (const float*)d_in[7];
    float* out             = (float*)d_out;

    // 1) pack weights into g_pack/g_scal (device globals)
    prep_kernel<<<1, 256>>>(w1, b1, w2, b2, gnw, gnb);

    // 2) D2D memcpy into the constant bank (graph-capturable memcpy nodes)
    void* pp = nullptr;
    void* ps = nullptr;
    cudaGetSymbolAddress(&pp, g_pack);
    cudaGetSymbolAddress(&ps, g_scal);
    cudaMemcpyToSymbolAsync(cwc, pp, sizeof(u64) * PACKN, 0,
                            cudaMemcpyDeviceToDevice);
    cudaMemcpyToSymbolAsync(csc, ps, sizeof(float) * 3 * LL * DD, 0,
                            cudaMemcpyDeviceToDevice);

    // 3) main kernel
    const int threads = TPB;
    const int blocks  = (PTS + threads - 1) / threads;
    atom_emb_mp_kernel<<<blocks, threads>>>(dist, atomtypes, out);
}